// round 10
// baseline (speedup 1.0000x reference)
#include <cuda_runtime.h>

#define H 256
#define P_PATHS 32768
#define LMAX 16
#define KDIM 288            // 256 path_emb + 8 edge + 16 scalar + 8 zero pad
#define NSTAGES 36          // KDIM / 8
#define MTILE 32            // paths per tile
#define NCOLS 128           // output cols per block (half of H)
#define HALF_TILES (P_PATHS / MTILE)   // 1024 tiles per half
#define GRID 152
#define THREADS 256

// ---------------- persistent scratch (no allocations allowed) ----------------
__device__ __align__(128) float g_Wf[KDIM * H];     // packed W1 tail (k-major, zero-padded)
__device__ __align__(128) float g_cpart[8][H];      // partial src/dst + b1 contribution
__device__ int g_ticket2[2];                        // per-half dynamic tile tickets

// ---------------- packed f32x2 helpers (sm_103a FFMA2 path) ----------------
typedef unsigned long long u64;
__device__ __forceinline__ u64 pack2(float x, float y) {
    u64 r; asm("mov.b64 %0, {%1, %2};" : "=l"(r) : "f"(x), "f"(y)); return r;
}
__device__ __forceinline__ void unpack2(u64 v, float& x, float& y) {
    asm("mov.b64 {%0, %1}, %2;" : "=f"(x), "=f"(y) : "l"(v));
}
__device__ __forceinline__ void ffma2(u64& d, u64 a, u64 b) {
    asm("fma.rn.f32x2 %0, %1, %2, %0;" : "+l"(d) : "l"(a), "l"(b));
}

// bank swizzle for the k-major A tile (32-float rows): permute 4-col groups per 8-k block
__device__ __forceinline__ int swz(int k) { return ((k >> 3) & 7) << 2; }

// ---------------- kernel 1: prep = pack Wf + c partials + ticket reset + out zero ----------------
// fused layout: [src 0:256 | dst 256:512 | path_emb 512:768 | edge 768:776 | scalar 776:792]
__global__ void prep_kernel(const float* __restrict__ W1,
                            const float* __restrict__ node_embs,
                            const float* __restrict__ b1,
                            const int* __restrict__ src_idx,
                            const int* __restrict__ dst_idx,
                            float* __restrict__ out) {
    int bid = blockIdx.x;
    int j = threadIdx.x;     // 0..255
    if (bid == 0 && j < 2) g_ticket2[j] = 0;
    if (bid < KDIM) {
        int k = bid;
        float v = 0.f;
        if (k < 256)       v = W1[(512 + k) * H + j];
        else if (k < 264)  v = W1[(768 + (k - 256)) * H + j];
        else if (k < 280)  v = W1[(776 + (k - 264)) * H + j];
        g_Wf[k * H + j] = v;
    } else if (bid < KDIM + 8) {
        int b = bid - KDIM;  // 0..7 : k slice [b*32, b*32+32)
        const float* s = node_embs + (long)(*src_idx) * H;
        const float* d = node_embs + (long)(*dst_idx) * H;
        float acc = (b == 0) ? b1[j] : 0.f;
        int k0 = b * 32;
#pragma unroll 8
        for (int k = k0; k < k0 + 32; k++) {
            acc = fmaf(s[k], W1[k * H + j], acc);
            acc = fmaf(d[k], W1[(256 + k) * H + j], acc);
        }
        g_cpart[b][j] = acc;
    } else {
        out[(bid - (KDIM + 8)) * 256 + j] = 0.f;   // 128 blocks x 256 = 32768
    }
}

// ---------------- gather: one path mean, warp-collective ----------------
__device__ __forceinline__ void gather_path(float* __restrict__ Asw,
                                            const float* __restrict__ node_embs,
                                            const int* __restrict__ path_nodes,
                                            const int* __restrict__ path_lens,
                                            int p, int pl, int lane) {
    int len = path_lens[p];
    const int4* nb = (const int4*)(path_nodes + (size_t)p * LMAX);
    int4 q0 = nb[0], q1 = nb[1], q2 = nb[2], q3 = nb[3];
    int ids[16] = {q0.x, q0.y, q0.z, q0.w, q1.x, q1.y, q1.z, q1.w,
                   q2.x, q2.y, q2.z, q2.w, q3.x, q3.y, q3.z, q3.w};
    float4 a0 = make_float4(0.f, 0.f, 0.f, 0.f);
    float4 a1 = make_float4(0.f, 0.f, 0.f, 0.f);
#pragma unroll
    for (int l = 0; l < LMAX; l++) {
        if (l < len) {
            const float4* r = (const float4*)(node_embs + (size_t)ids[l] * H);
            float4 v0 = r[lane];
            float4 v1 = r[32 + lane];
            a0.x += v0.x; a0.y += v0.y; a0.z += v0.z; a0.w += v0.w;
            a1.x += v1.x; a1.y += v1.y; a1.z += v1.z; a1.w += v1.w;
        }
    }
    float inv = 1.f / (float)max(len, 1);
    int k0 = 4 * lane;
    float va0[4] = {a0.x, a0.y, a0.z, a0.w};
    float va1[4] = {a1.x, a1.y, a1.z, a1.w};
#pragma unroll
    for (int j = 0; j < 4; j++) {
        int ka = k0 + j, kb = 128 + k0 + j;
        Asw[ka * MTILE + (pl ^ swz(ka))] = va0[j] * inv;
        Asw[kb * MTILE + (pl ^ swz(kb))] = va1[j] * inv;
    }
}

// edge + scalar rows (k = 256..279) for one path, one thread
__device__ __forceinline__ void edge_rows(float* __restrict__ Asw,
                                          const float* __restrict__ edge_feats,
                                          const float* __restrict__ scalar_feats,
                                          int p, int pl) {
    const float4* ef = (const float4*)(edge_feats + (size_t)p * 8);
    float4 e0 = ef[0], e1 = ef[1];
    const float4* sf = (const float4*)(scalar_feats + (size_t)p * 16);
    float4 s0 = sf[0], s1 = sf[1], s2 = sf[2], s3 = sf[3];
    float ev[8]  = {e0.x, e0.y, e0.z, e0.w, e1.x, e1.y, e1.z, e1.w};
    float sv[16] = {s0.x, s0.y, s0.z, s0.w, s1.x, s1.y, s1.z, s1.w,
                    s2.x, s2.y, s2.z, s2.w, s3.x, s3.y, s3.z, s3.w};
#pragma unroll
    for (int e = 0; e < 8; e++) {
        int k = 256 + e;
        Asw[k * MTILE + (pl ^ swz(k))] = ev[e];
    }
#pragma unroll
    for (int f = 0; f < 16; f++) {
        int k = 264 + f;
        Asw[k * MTILE + (pl ^ swz(k))] = sv[f];
    }
}

// ---------------- barrier-free inner GEMM over one tile (B resident in smem) ----------------
__device__ __forceinline__ void gemm_tile(const float* __restrict__ Asr,
                                          const float* __restrict__ Bsm,
                                          int grow, int gcol, u64 (&acc)[4][2]) {
#pragma unroll 1
    for (int k8 = 0; k8 < NSTAGES; k8++) {
        int sw = (k8 & 7) << 2;
        const float* Ap = Asr + k8 * 8 * MTILE + (grow ^ sw);
        const float* Bp = Bsm + k8 * 8 * NCOLS + gcol;
#pragma unroll
        for (int kk = 0; kk < 8; kk++) {
            float4 a = *(const float4*)(Ap + kk * MTILE);
            ulonglong2 b = *(const ulonglong2*)(Bp + kk * NCOLS);
            float av[4] = {a.x, a.y, a.z, a.w};
#pragma unroll
            for (int i = 0; i < 4; i++) {
                u64 ad = pack2(av[i], av[i]);
                ffma2(acc[i][0], ad, b.x);
                ffma2(acc[i][1], ad, b.y);
            }
        }
    }
}

// ---------------- kernel 2: persistent, N-split, barrier-free-mainloop pipeline ----------------
__global__ __launch_bounds__(THREADS, 1)
void fused_kernel(const float* __restrict__ node_embs,
                  const int*   __restrict__ path_nodes,
                  const int*   __restrict__ path_lens,
                  const float* __restrict__ edge_feats,
                  const float* __restrict__ scalar_feats,
                  const float* __restrict__ W2,
                  const float* __restrict__ b2,
                  float*       __restrict__ out) {
    extern __shared__ float sm[];
    float* Bsm = sm;                           // [KDIM][128]      147456 B (this half's W1)
    float* As  = Bsm + KDIM * NCOLS;           // [2][KDIM][32]     73728 B
    float* cs  = As + 2 * KDIM * MTILE;        // [128]
    float* w2s = cs + NCOLS;                   // [128]
    float* qp  = w2s + NCOLS;                  // [32][33]           4224 B
    __shared__ int s_nxt[2];

    int t = threadIdx.x;
    int w = t >> 5, lane = t & 31;
    int half = blockIdx.x & 1;

    if (t == 0) s_nxt[0] = atomicAdd(&g_ticket2[half], 1);

    // B resident load: 288 rows x 128 cols of this half
    {
        const float4* src = (const float4*)g_Wf;
        float4* dst = (float4*)Bsm;
#pragma unroll 4
        for (int i = t; i < KDIM * NCOLS / 4; i += THREADS) {
            int k = i >> 5, j4 = i & 31;       // 32 float4 per row
            dst[i] = src[k * 64 + half * 32 + j4];
        }
    }
    // constants for this half
    if (t < NCOLS) {
        float cv = 0.f;
#pragma unroll
        for (int b = 0; b < 8; b++) cv += g_cpart[b][half * NCOLS + t];
        cs[t]  = cv;
        w2s[t] = W2[half * NCOLS + t];
    }
    // zero-pad rows (k = 280..287), both buffers
    if (t < MTILE) {
#pragma unroll
        for (int z = 0; z < 8; z++) {
            int k = 280 + z;
            As[k * MTILE + (t ^ swz(k))] = 0.f;
            As[KDIM * MTILE + k * MTILE + (t ^ swz(k))] = 0.f;
        }
    }
    __syncthreads();

    int cur = s_nxt[0];
    if (cur >= HALF_TILES) return;             // late-scheduled block: nothing left

    // prologue: gather first tile into buf 0
#pragma unroll 1
    for (int pi = 0; pi < 4; pi++)
        gather_path(As, node_embs, path_nodes, path_lens,
                    cur * MTILE + 4 * w + pi, 4 * w + pi, lane);
    if (t < MTILE)
        edge_rows(As, edge_feats, scalar_feats, cur * MTILE + t, t);
    if (t == 0) s_nxt[1] = atomicAdd(&g_ticket2[half], 1);
    __syncthreads();

    // GEMM thread mapping: 8 warps over 32x128, warp tile 16x32, thread tile 4x4
    int grow = 16 * (w & 1) + 4 * (lane >> 3);   // 0..28
    int gcol = 32 * (w >> 1) + 4 * (lane & 7);   // 0..124
    int cg   = gcol >> 2;                        // 0..31

    int buf = 0;
    while (true) {
        int nxt = s_nxt[buf ^ 1];
        bool hasNext = (nxt < HALF_TILES);
        if (hasNext && t == 0) s_nxt[buf] = atomicAdd(&g_ticket2[half], 1);

        const float* Asr = As + buf * (KDIM * MTILE);
        float*       Asw = As + (buf ^ 1) * (KDIM * MTILE);

        u64 acc[4][2];
#pragma unroll
        for (int i = 0; i < 4; i++) { acc[i][0] = 0ull; acc[i][1] = 0ull; }

        if (w < 4) {
            if (hasNext) {
#pragma unroll 1
                for (int pi = 0; pi < 4; pi++)
                    gather_path(Asw, node_embs, path_nodes, path_lens,
                                nxt * MTILE + 4 * w + pi, 4 * w + pi, lane);
                if (t < MTILE)
                    edge_rows(Asw, edge_feats, scalar_feats, nxt * MTILE + t, t);
            }
            gemm_tile(Asr, Bsm, grow, gcol, acc);
        } else {
            gemm_tile(Asr, Bsm, grow, gcol, acc);
            if (hasNext) {
#pragma unroll 1
                for (int pi = 0; pi < 4; pi++)
                    gather_path(Asw, node_embs, path_nodes, path_lens,
                                nxt * MTILE + 4 * w + pi, 4 * w + pi, lane);
            }
        }

        // epilogue: +c, relu, dot(W2) partials
#pragma unroll
        for (int i = 0; i < 4; i++) {
            float v0, v1, v2, v3;
            unpack2(acc[i][0], v0, v1);
            unpack2(acc[i][1], v2, v3);
            v0 = fmaxf(v0 + cs[gcol],     0.f);
            v1 = fmaxf(v1 + cs[gcol + 1], 0.f);
            v2 = fmaxf(v2 + cs[gcol + 2], 0.f);
            v3 = fmaxf(v3 + cs[gcol + 3], 0.f);
            float si;
            si = v0 * w2s[gcol];
            si = fmaf(v1, w2s[gcol + 1], si);
            si = fmaf(v2, w2s[gcol + 2], si);
            si = fmaf(v3, w2s[gcol + 3], si);
            qp[(grow + i) * 33 + cg] = si;
        }
        __syncthreads();

        if (t < MTILE) {
            int p = cur * MTILE + t;
            float sv = (half == 0) ? b2[0] : 0.f;
#pragma unroll
            for (int j = 0; j < 32; j++) sv += qp[t * 33 + j];
            atomicAdd(&out[p], (path_lens[p] > 0) ? sv : 0.f);
        }

        if (!hasNext) break;
        cur = nxt; buf ^= 1;
        __syncthreads();
    }
}

// ---------------- launch ----------------
#define FUSED_SMEM ((KDIM * NCOLS + 2 * KDIM * MTILE + NCOLS + NCOLS + 32 * 33) * (int)sizeof(float))

extern "C" void kernel_launch(void* const* d_in, const int* in_sizes, int n_in,
                              void* d_out, int out_size) {
    const float* node_embs    = (const float*)d_in[0];
    const int*   path_nodes   = (const int*)  d_in[1];
    const int*   path_lens    = (const int*)  d_in[2];
    const float* edge_feats   = (const float*)d_in[3];
    const float* scalar_feats = (const float*)d_in[4];
    const float* W1           = (const float*)d_in[5];
    const float* b1           = (const float*)d_in[6];
    const float* W2           = (const float*)d_in[7];
    const float* b2           = (const float*)d_in[8];
    const int*   src_idx      = (const int*)  d_in[9];
    const int*   dst_idx      = (const int*)  d_in[10];
    float* out = (float*)d_out;

    cudaFuncSetAttribute(fused_kernel,
                         cudaFuncAttributeMaxDynamicSharedMemorySize, FUSED_SMEM);

    prep_kernel<<<KDIM + 8 + 128, H>>>(W1, node_embs, b1, src_idx, dst_idx, out);
    fused_kernel<<<GRID, THREADS, FUSED_SMEM>>>(
        node_embs, path_nodes, path_lens, edge_feats, scalar_feats, W2, b2, out);
}

// round 12
// speedup vs baseline: 2.1188x; 2.1188x over previous
#include <cuda_runtime.h>
#include <cuda_bf16.h>
#include <cstdint>

#define H 256
#define P_PATHS 32768
#define LMAX 16
#define NKS 18                 // k-steps of 16 (K = 288 = 256 emb + 8 edge + 16 scalar + 8 zero)
#define MTILE 64               // paths per block
#define NT (P_PATHS / MTILE)   // 512 blocks
#define THREADS 256

// ---- dynamic smem byte offsets ----
#define ASTRB 592              // A row stride bytes (296 halves; 37 segs, odd -> conflict-free ldsm)
#define BSTRB 528              // B k-row stride bytes (264 halves; 33 segs, odd)
#define OFF_AH 0
#define OFF_AL 37888           // 64*592
#define OFF_B  75776
#define BSPL   8448            // 16*528 per split
#define OFF_CS 92672
#define OFF_W2 93696
#define OFF_QP 94720           // float[64][17]
#define SMEM_BYTES 99072

// ---------------- persistent scratch ----------------
__device__ __align__(128) unsigned g_Bh[NKS * 2048];   // [chunk][k(16)][n2(128)] bf16x2 (n-pairs)
__device__ __align__(128) unsigned g_Bl[NKS * 2048];
__device__ __align__(128) float g_cpart[8][H];

// ---------------- helpers ----------------
__device__ __forceinline__ uint32_t smem_u32(const void* p) {
    uint32_t a;
    asm("{ .reg .u64 t; cvta.to.shared.u64 t, %1; cvt.u32.u64 %0, t; }" : "=r"(a) : "l"(p));
    return a;
}
__device__ __forceinline__ void split2(float a, float b, unsigned& h, unsigned& l) {
    __nv_bfloat16 ha = __float2bfloat16_rn(a), hb = __float2bfloat16_rn(b);
    float ra = a - __bfloat162float(ha), rb = b - __bfloat162float(hb);
    __nv_bfloat16 la = __float2bfloat16_rn(ra), lb = __float2bfloat16_rn(rb);
    h = (unsigned)__bfloat16_as_ushort(ha) | ((unsigned)__bfloat16_as_ushort(hb) << 16);
    l = (unsigned)__bfloat16_as_ushort(la) | ((unsigned)__bfloat16_as_ushort(lb) << 16);
}
__device__ __forceinline__ void ldsm4(unsigned* r, uint32_t a) {
    asm volatile("ldmatrix.sync.aligned.m8n8.x4.shared.b16 {%0,%1,%2,%3}, [%4];"
                 : "=r"(r[0]), "=r"(r[1]), "=r"(r[2]), "=r"(r[3]) : "r"(a));
}
__device__ __forceinline__ void ldsm4t(unsigned* r, uint32_t a) {
    asm volatile("ldmatrix.sync.aligned.m8n8.x4.trans.shared.b16 {%0,%1,%2,%3}, [%4];"
                 : "=r"(r[0]), "=r"(r[1]), "=r"(r[2]), "=r"(r[3]) : "r"(a));
}
__device__ __forceinline__ void mma_bf16(float* d, const unsigned* a, unsigned b0, unsigned b1) {
    asm volatile("mma.sync.aligned.m16n8k16.row.col.f32.bf16.bf16.f32 "
                 "{%0,%1,%2,%3}, {%4,%5,%6,%7}, {%8,%9}, {%0,%1,%2,%3};"
                 : "+f"(d[0]), "+f"(d[1]), "+f"(d[2]), "+f"(d[3])
                 : "r"(a[0]), "r"(a[1]), "r"(a[2]), "r"(a[3]), "r"(b0), "r"(b1));
}

// fused-k -> W1 row: [src 0:256 | dst 256:512 | emb 512:768 | edge 768:776 | scalar 776:792]
__device__ __forceinline__ float wfused(const float* W1, int kg, int j) {
    if (kg < 256) return W1[(512 + kg) * H + j];
    if (kg < 264) return W1[(768 + (kg - 256)) * H + j];
    if (kg < 280) return W1[(776 + (kg - 264)) * H + j];
    return 0.f;
}

// ---------------- kernel 1: prep (pack bf16 hi/lo W chunks, c partials) ----------------
__global__ void prep_kernel(const float* __restrict__ W1,
                            const float* __restrict__ node_embs,
                            const float* __restrict__ b1,
                            const int* __restrict__ src_idx,
                            const int* __restrict__ dst_idx) {
    int bid = blockIdx.x;
    int t = threadIdx.x;        // 0..255
    if (bid < NKS) {
        int c = bid;
        int kk = t >> 7;        // 0..1
        int n2 = t & 127;       // u32 (n-pair) index
#pragma unroll
        for (int i = 0; i < 8; i++) {
            int k = i * 2 + kk;
            int kg = c * 16 + k;
            float v0 = wfused(W1, kg, 2 * n2);
            float v1 = wfused(W1, kg, 2 * n2 + 1);
            unsigned hp, lp; split2(v0, v1, hp, lp);
            int idx = c * 2048 + k * 128 + n2;
            g_Bh[idx] = hp;
            g_Bl[idx] = lp;
        }
    } else {
        int b = bid - NKS;      // 0..7
        const float* s = node_embs + (long)(*src_idx) * H;
        const float* d = node_embs + (long)(*dst_idx) * H;
        float acc = (b == 0) ? b1[t] : 0.f;
        int k0 = b * 32;
#pragma unroll 8
        for (int k = k0; k < k0 + 32; k++) {
            acc = fmaf(s[k], W1[k * H + t], acc);
            acc = fmaf(d[k], W1[(256 + k) * H + t], acc);
        }
        g_cpart[b][t] = acc;
    }
}

// ---------------- gather: one path mean -> bf16 hi/lo rows of A ----------------
__device__ __forceinline__ void gather_path(char* __restrict__ Ah, char* __restrict__ Al,
                                            const float* __restrict__ node_embs,
                                            const int* __restrict__ path_nodes,
                                            const int* __restrict__ path_lens,
                                            int p, int pl, int lane) {
    int len = path_lens[p];
    const int4* nb = (const int4*)(path_nodes + (size_t)p * LMAX);
    int4 q0 = nb[0], q1 = nb[1], q2 = nb[2], q3 = nb[3];
    int ids[16] = {q0.x, q0.y, q0.z, q0.w, q1.x, q1.y, q1.z, q1.w,
                   q2.x, q2.y, q2.z, q2.w, q3.x, q3.y, q3.z, q3.w};
    float4 a0 = make_float4(0.f, 0.f, 0.f, 0.f);
    float4 a1 = make_float4(0.f, 0.f, 0.f, 0.f);
#pragma unroll
    for (int l = 0; l < LMAX; l++) {
        if (l < len) {
            const float4* r = (const float4*)(node_embs + (size_t)ids[l] * H);
            float4 v0 = r[lane];          // k = 4*lane ..
            float4 v1 = r[32 + lane];     // k = 128 + 4*lane ..
            a0.x += v0.x; a0.y += v0.y; a0.z += v0.z; a0.w += v0.w;
            a1.x += v1.x; a1.y += v1.y; a1.z += v1.z; a1.w += v1.w;
        }
    }
    float inv = 1.f / (float)max(len, 1);
    unsigned h01, l01, h23, l23;
    split2(a0.x * inv, a0.y * inv, h01, l01);
    split2(a0.z * inv, a0.w * inv, h23, l23);
    *(uint2*)(Ah + pl * ASTRB + lane * 8) = make_uint2(h01, h23);
    *(uint2*)(Al + pl * ASTRB + lane * 8) = make_uint2(l01, l23);
    split2(a1.x * inv, a1.y * inv, h01, l01);
    split2(a1.z * inv, a1.w * inv, h23, l23);
    *(uint2*)(Ah + pl * ASTRB + 256 + lane * 8) = make_uint2(h01, h23);
    *(uint2*)(Al + pl * ASTRB + 256 + lane * 8) = make_uint2(l01, l23);
}

__device__ __forceinline__ void sts_bchunk(char* Bbase, int i, uint4 v) {
    int k = i >> 5, seg = i & 31;
    *(uint4*)(Bbase + k * BSTRB + seg * 16) = v;
}

// ---------------- kernel 2: fused gather + bf16 HMMA GEMM + relu.W2 epilogue ----------------
__global__ __launch_bounds__(THREADS, 2)
void fused_kernel(const float* __restrict__ node_embs,
                  const int*   __restrict__ path_nodes,
                  const int*   __restrict__ path_lens,
                  const float* __restrict__ edge_feats,
                  const float* __restrict__ scalar_feats,
                  const float* __restrict__ W2,
                  const float* __restrict__ b2,
                  float*       __restrict__ out) {
    extern __shared__ __align__(16) char smc[];
    char* Ah = smc + OFF_AH;
    char* Al = smc + OFF_AL;
    char* Bb = smc + OFF_B;
    float* cs  = (float*)(smc + OFF_CS);
    float* w2s = (float*)(smc + OFF_W2);
    float* qp  = (float*)(smc + OFF_QP);

    int t = threadIdx.x;
    int w = t >> 5, lane = t & 31;
    int p0 = blockIdx.x * MTILE;
    uint32_t sb = smem_u32(smc);

    // constants
    {
        float cv = 0.f;
#pragma unroll
        for (int b = 0; b < 8; b++) cv += g_cpart[b][t];
        cs[t]  = cv;
        w2s[t] = W2[t];
    }

    // ---- phase 1: gather 64 paths (8 per warp) into bf16 hi/lo A ----
#pragma unroll 1
    for (int pi = 0; pi < 8; pi++)
        gather_path(Ah, Al, node_embs, path_nodes, path_lens,
                    p0 + 8 * w + pi, 8 * w + pi, lane);

    // edge/scalar/zero rows: halves 256..287 of path t
    if (t < MTILE) {
        int p = p0 + t;
        const float4* ef = (const float4*)(edge_feats + (size_t)p * 8);
        float4 e0 = ef[0], e1 = ef[1];
        const float4* sf = (const float4*)(scalar_feats + (size_t)p * 16);
        float4 s0 = sf[0], s1 = sf[1], s2 = sf[2], s3 = sf[3];
        float v[24] = {e0.x, e0.y, e0.z, e0.w, e1.x, e1.y, e1.z, e1.w,
                       s0.x, s0.y, s0.z, s0.w, s1.x, s1.y, s1.z, s1.w,
                       s2.x, s2.y, s2.z, s2.w, s3.x, s3.y, s3.z, s3.w};
        unsigned hi[16], lo[16];
#pragma unroll
        for (int j = 0; j < 12; j++) split2(v[2 * j], v[2 * j + 1], hi[j], lo[j]);
#pragma unroll
        for (int j = 12; j < 16; j++) { hi[j] = 0u; lo[j] = 0u; }
#pragma unroll
        for (int j = 0; j < 4; j++) {
            *(uint4*)(Ah + t * ASTRB + 512 + 16 * j) =
                make_uint4(hi[4 * j], hi[4 * j + 1], hi[4 * j + 2], hi[4 * j + 3]);
            *(uint4*)(Al + t * ASTRB + 512 + 16 * j) =
                make_uint4(lo[4 * j], lo[4 * j + 1], lo[4 * j + 2], lo[4 * j + 3]);
        }
    }

    // ---- B chunk 0 prologue ----
    const uint4* gBh4 = (const uint4*)g_Bh;
    const uint4* gBl4 = (const uint4*)g_Bl;
    {
        uint4 h0 = gBh4[t], h1 = gBh4[t + 256];
        uint4 l0 = gBl4[t], l1 = gBl4[t + 256];
        sts_bchunk(Bb,        t,       h0);
        sts_bchunk(Bb,        t + 256, h1);
        sts_bchunk(Bb + BSPL, t,       l0);
        sts_bchunk(Bb + BSPL, t + 256, l1);
    }
    __syncthreads();   // A + B0 + constants visible

    // ---- phase 2: GEMM. warp tile 32 rows x 64 cols ----
    int wr = w & 1, wc = w >> 1;                       // 2 row groups, 4 col groups
    // A ldmatrix lane address (tile0; tile1 = +16*ASTRB; lo split = +(OFF_AL-OFF_AH))
    uint32_t a_base = sb + OFF_AH + (uint32_t)(wr * 32 + (lane & 15)) * ASTRB + ((lane >> 4) << 4);
    // B ldmatrix.trans lane address (pair 0; pair p = +32*p; lo split = +BSPL)
    int bk = (lane & 7) + ((lane >> 4) << 3);
    int bn = wc * 64 + (((lane >> 3) & 1) << 3);
    uint32_t b_base = sb + OFF_B + (uint32_t)bk * BSTRB + (uint32_t)bn * 2;

    float d[2][8][4];
#pragma unroll
    for (int i = 0; i < 2; i++)
#pragma unroll
        for (int j = 0; j < 8; j++)
#pragma unroll
            for (int q = 0; q < 4; q++) d[i][j][q] = 0.f;

#pragma unroll 1
    for (int s = 0; s < NKS; s++) {
        uint4 nh0, nh1, nl0, nl1;
        if (s + 1 < NKS) {
            nh0 = gBh4[(s + 1) * 512 + t];
            nh1 = gBh4[(s + 1) * 512 + t + 256];
            nl0 = gBl4[(s + 1) * 512 + t];
            nl1 = gBl4[(s + 1) * 512 + t + 256];
        }
        unsigned ah[2][4], al[2][4];
        ldsm4(ah[0], a_base + s * 32);
        ldsm4(ah[1], a_base + 16 * ASTRB + s * 32);
        ldsm4(al[0], a_base + (OFF_AL - OFF_AH) + s * 32);
        ldsm4(al[1], a_base + (OFF_AL - OFF_AH) + 16 * ASTRB + s * 32);
#pragma unroll
        for (int pr = 0; pr < 4; pr++) {
            unsigned bh[4], bl[4];
            ldsm4t(bh, b_base + pr * 32);
            ldsm4t(bl, b_base + BSPL + pr * 32);
            int n0 = pr * 2, n1 = n0 + 1;
            // hi*hi
            mma_bf16(d[0][n0], ah[0], bh[0], bh[2]);
            mma_bf16(d[0][n1], ah[0], bh[1], bh[3]);
            mma_bf16(d[1][n0], ah[1], bh[0], bh[2]);
            mma_bf16(d[1][n1], ah[1], bh[1], bh[3]);
            // hi*lo
            mma_bf16(d[0][n0], ah[0], bl[0], bl[2]);
            mma_bf16(d[0][n1], ah[0], bl[1], bl[3]);
            mma_bf16(d[1][n0], ah[1], bl[0], bl[2]);
            mma_bf16(d[1][n1], ah[1], bl[1], bl[3]);
            // lo*hi
            mma_bf16(d[0][n0], al[0], bh[0], bh[2]);
            mma_bf16(d[0][n1], al[0], bh[1], bh[3]);
            mma_bf16(d[1][n0], al[1], bh[0], bh[2]);
            mma_bf16(d[1][n1], al[1], bh[1], bh[3]);
        }
        __syncthreads();                 // all warps done reading B chunk s
        if (s + 1 < NKS) {
            sts_bchunk(Bb,        t,       nh0);
            sts_bchunk(Bb,        t + 256, nh1);
            sts_bchunk(Bb + BSPL, t,       nl0);
            sts_bchunk(Bb + BSPL, t + 256, nl1);
            __syncthreads();             // chunk s+1 ready
        }
    }

    // ---- epilogue: +c, relu, dot(W2) partials ----
    int slot = (wc << 2) | (lane & 3);   // 0..15
#pragma unroll
    for (int at = 0; at < 2; at++) {
        float qa = 0.f, qb = 0.f;
#pragma unroll
        for (int nt = 0; nt < 8; nt++) {
            int jg = wc * 64 + nt * 8 + 2 * (lane & 3);
            float c0 = cs[jg], c1 = cs[jg + 1];
            float w0 = w2s[jg], w1 = w2s[jg + 1];
            qa = fmaf(fmaxf(d[at][nt][0] + c0, 0.f), w0, qa);
            qa = fmaf(fmaxf(d[at][nt][1] + c1, 0.f), w1, qa);
            qb = fmaf(fmaxf(d[at][nt][2] + c0, 0.f), w0, qb);
            qb = fmaf(fmaxf(d[at][nt][3] + c1, 0.f), w1, qb);
        }
        int r = wr * 32 + at * 16 + (lane >> 2);
        qp[r * 17 + slot]       = qa;
        qp[(r + 8) * 17 + slot] = qb;
    }
    __syncthreads();

    if (t < MTILE) {
        int p = p0 + t;
        float sv = b2[0];
#pragma unroll
        for (int j = 0; j < 16; j++) sv += qp[t * 17 + j];
        out[p] = (path_lens[p] > 0) ? sv : 0.f;
    }
}

// ---------------- launch ----------------
extern "C" void kernel_launch(void* const* d_in, const int* in_sizes, int n_in,
                              void* d_out, int out_size) {
    const float* node_embs    = (const float*)d_in[0];
    const int*   path_nodes   = (const int*)  d_in[1];
    const int*   path_lens    = (const int*)  d_in[2];
    const float* edge_feats   = (const float*)d_in[3];
    const float* scalar_feats = (const float*)d_in[4];
    const float* W1           = (const float*)d_in[5];
    const float* b1           = (const float*)d_in[6];
    const float* W2           = (const float*)d_in[7];
    const float* b2           = (const float*)d_in[8];
    const int*   src_idx      = (const int*)  d_in[9];
    const int*   dst_idx      = (const int*)  d_in[10];
    float* out = (float*)d_out;

    cudaFuncSetAttribute(fused_kernel,
                         cudaFuncAttributeMaxDynamicSharedMemorySize, SMEM_BYTES);

    prep_kernel<<<NKS + 8, H>>>(W1, node_embs, b1, src_idx, dst_idx);
    fused_kernel<<<NT, THREADS, SMEM_BYTES>>>(
        node_embs, path_nodes, path_lens, edge_feats, scalar_feats, W2, b2, out);
}